// round 14
// baseline (speedup 1.0000x reference)
#include <cuda_runtime.h>
#include <math.h>

#define HH 480
#define WW 640
#define NPIX (HH*WW)          // 307200
#define MM 960
#define MPIX (MM*MM)          // 921600
#define FP_OFF 0
#define MAP_OFF 10000
#define POSE_OFF (10000 + 9*MPIX)   // 8304400
#define SPLAT_BLOCKS 1200
#define COPY_BLOCKS 8100      // 9 ch * 230400 quads / 256
#define FUSED_BLOCKS 9300     // 31 * 300 (4 splat + 27 copy per group)
#define ROT_LO 360
#define ROT_W 241             // covers [360,600] inclusive
#define ZW 12                 // window z slots: 13..24
#define VQ (MPIX/4)           // 230400 quads per channel
#define FIXW 192              // fix window (pixels), 48 quads per row
#define FIX_THREADS (7*48*FIXW)   // 64512

// scratch (device globals: allocation-free, zero-initialized at load)
__device__ __align__(16) float g_voxw[100*100*80];      // scalar weight grid, full z (3.2MB)
__device__ __align__(32) float g_voxf[100*100*ZW*8];    // window: [col][wz][8] = w,f1..f5,pad,pad
__device__ float g_av[7*10000];                // agent_view active region, ch {0,1,4,5,6,7,8}
__device__ float g_rot[7*MPIX];                // rotated image (only support window ever written)
__device__ float g_bmax[4*SPLAT_BLOCKS];       // per-block ks maxes
__device__ float g_ks[4];                      // final ks
__device__ float g_params[12];                 // 0:fcam 1:ct 2:sn 3:sx 4:sy 5..8:bbox 9:dxs 10:dys
__device__ int   g_win[2];                     // fix window origin (ox, oy)

__device__ __forceinline__ void red_v4(float* p, float a, float b, float c, float d) {
    asm volatile("red.global.add.v4.f32 [%0], {%1,%2,%3,%4};"
                 :: "l"(p), "f"(a), "f"(b), "f"(c), "f"(d) : "memory");
}
__device__ __forceinline__ void red_v2(float* p, float a, float b) {
    asm volatile("red.global.add.v2.f32 [%0], {%1,%2};"
                 :: "l"(p), "f"(a), "f"(b) : "memory");
}
__device__ __forceinline__ void red_f(float* p, float a) {
    asm volatile("red.global.add.f32 [%0], %1;" :: "l"(p), "f"(a) : "memory");
}

// dirty-quad predicate: MUST be evaluated on g_params values by both the copy
// path and the fix kernel (identical inputs -> identical boolean; float
// compares are exact). Margin 2 + bbox's own margin 3 absorb sampling-ulp drift.
__device__ __forceinline__ bool quad_dirty(int i, int j0,
                                           float xminf, float xmaxf,
                                           float yminf, float ymaxf,
                                           float dxs, float dys) {
    float ylo = floorf((float)i + dys);
    float xlo = floorf((float)j0 + dxs);
    float xhi = floorf((float)(j0+3) + dxs);
    return (ylo >= yminf - 2.0f) && (ylo <= ymaxf + 2.0f) &&
           (xhi >= xminf - 2.0f) && (xlo <= xmaxf + 2.0f);
}

// ---------------------------------------------------------------- pose/params (single thread)
__global__ void pose_kernel(const float* __restrict__ pose_obs,
                            const float* __restrict__ poses_last,
                            float* __restrict__ out) {
    const float DEGf = 57.29577951308232f;
    float th = poses_last[2] / DEGf;
    float s = sinf(th), c = cosf(th);
    float ny = poses_last[1] + pose_obs[0]*s + pose_obs[1]*c;
    float nx = poses_last[0] + pose_obs[0]*c - pose_obs[1]*s;
    float nt = poses_last[2] + pose_obs[2]*DEGf;
    nt = fmodf(nt - 180.0f, 360.0f) + 180.0f;
    nt = fmodf(nt + 180.0f, 360.0f) - 180.0f;
    out[POSE_OFF+0] = nx; out[POSE_OFF+1] = ny; out[POSE_OFF+2] = nt;
    out[POSE_OFF+3] = nx; out[POSE_OFF+4] = ny; out[POSE_OFF+5] = nt;

    float sx = -(nx*100.0f/5.0f - 480.0f)/480.0f;
    float sy = -(ny*100.0f/5.0f - 480.0f)/480.0f;
    float sth = (90.0f - nt) * 3.14159265358979323846f / 180.0f;
    float ct = cosf(sth), sn = sinf(sth);
    g_params[0] = (float)(320.0 / tan(39.5 * 3.141592653589793 / 180.0));
    g_params[1] = ct; g_params[2] = sn;
    g_params[3] = sx; g_params[4] = sy;

    const float half = 479.5f;
    float xmn=1e9f,xmx=-1e9f,ymn=1e9f,ymx=-1e9f;
    float cx[4] = {429.f,530.f,429.f,530.f};
    float cy[4] = {479.f,479.f,580.f,580.f};
    #pragma unroll
    for (int k=0;k<4;k++){
        float u = cx[k]/half - 1.0f, v = cy[k]/half - 1.0f;
        float gu =  ct*u + sn*v;
        float gv = -sn*u + ct*v;
        float jx = (gu+1.0f)*half, iy = (gv+1.0f)*half;
        xmn = fminf(xmn,jx); xmx = fmaxf(xmx,jx);
        ymn = fminf(ymn,iy); ymx = fmaxf(ymx,iy);
    }
    float xminf = fmaxf(floorf(xmn)-3.0f, 0.0f);
    float xmaxf = fminf(ceilf (xmx)+3.0f, 959.0f);
    float yminf = fmaxf(floorf(ymn)-3.0f, 0.0f);
    float ymaxf = fminf(ceilf (ymx)+3.0f, 959.0f);
    g_params[5] = xminf; g_params[6] = xmaxf;
    g_params[7] = yminf; g_params[8] = ymaxf;
    float dxs = sx*479.5f, dys = sy*479.5f;
    g_params[9] = dxs; g_params[10] = dys;

    int ox = (((int)floorf(xminf - dxs)) - 8) & ~3;
    int oy =  ((int)floorf(yminf - dys)) - 8;
    ox = max(0, min(ox, MM - FIXW));
    oy = max(0, min(oy, MM - FIXW));
    g_win[0] = ox; g_win[1] = oy;
}

// ---------------------------------------------------------------- fused: splat + out-of-bbox map copy
__global__ __launch_bounds__(256) void fused_kernel(const float* __restrict__ obs,
                                                    const float* __restrict__ maps_last,
                                                    float* __restrict__ out_map) {
    int b = blockIdx.x;
    int grp = b / 31, r = b % 31;
    int tid = threadIdx.x;

    if (r >= 4) {
        // ================= copy path: one float4 of one channel per thread
        int cblock = grp*27 + (r - 4);
        int idx = cblock*256 + tid;          // [0, 9*VQ)
        int ch = idx / VQ;                   // uniform per block (VQ % 256 == 0)
        int q  = idx - ch*VQ;
        const float4* ml = reinterpret_cast<const float4*>(maps_last);
        float4*       om = reinterpret_cast<float4*>(out_map);
        if (ch != 2 && ch != 3) {
            int i  = q / (MM/4);
            int j0 = (q - i*(MM/4)) * 4;
            float xminf = g_params[5], xmaxf = g_params[6];
            float yminf = g_params[7], ymaxf = g_params[8];
            float dxs = g_params[9],  dys = g_params[10];
            int ox = g_win[0], oy = g_win[1];
            bool inwin = (i >= oy) && (i < oy + FIXW) && (j0 >= ox) && (j0 < ox + FIXW);
            if (inwin && quad_dirty(i, j0, xminf, xmaxf, yminf, ymaxf, dxs, dys))
                return;                       // fix_kernel owns this quad+channel
        }
        float4 m = ml[idx];
        om[idx] = make_float4(fmaxf(m.x,0.f), fmaxf(m.y,0.f), fmaxf(m.z,0.f), fmaxf(m.w,0.f));
        return;
    }

    // ================= splat path
    __shared__ float smax[8][4];
    int sblock = grp*4 + r;
    float fcam = g_params[0];
    int pix = sblock*256 + tid;              // NPIX == SPLAT_BLOCKS*256 exactly
    int i = pix / WW, j = pix - i*WW;
    float depth = obs[3*NPIX + pix];
    float X = ((float)j - 319.5f) * depth / fcam + 250.0f;
    float Z = ((float)(479 - i) - 239.5f) * depth / fcam + 88.0f;
    float xs = (X/5.0f - 50.0f)/100.0f*2.0f;
    float ys = (depth/5.0f - 50.0f)/100.0f*2.0f;
    float zs = (Z/5.0f - 32.0f)/80.0f*2.0f;
    float pos0 = xs*100.0f/2.0f + 50.0f;
    float pos1 = ys*100.0f/2.0f + 50.0f;
    float pos2 = zs*80.0f/2.0f + 40.0f;
    float fl0 = floorf(pos0), fl1 = floorf(pos1), fl2 = floorf(pos2);
    float ft1 = obs[4*NPIX+pix], ft2 = obs[5*NPIX+pix], ft3 = obs[6*NPIX+pix];
    float ft4 = obs[7*NPIX+pix], ft5 = obs[8*NPIX+pix];

    #pragma unroll
    for (int c0=0;c0<2;c0++){
        float p0 = fl0 + (float)c0;
        if (!(p0 > 0.0f && p0 < 100.0f)) continue;
        float w0 = 1.0f - fabsf(pos0 - p0);
        #pragma unroll
        for (int c1=0;c1<2;c1++){
            float p1 = fl1 + (float)c1;
            if (!(p1 > 0.0f && p1 < 100.0f)) continue;
            float w01 = w0 * (1.0f - fabsf(pos1 - p1));
            int col = ((int)p0)*100 + (int)p1;
            #pragma unroll
            for (int c2=0;c2<2;c2++){
                float p2 = fl2 + (float)c2;
                if (!(p2 > 0.0f && p2 < 80.0f)) continue;
                float w = w01 * (1.0f - fabsf(pos2 - p2));
                int z = (int)p2;
                if (z >= 13 && z < 25) {
                    float* base = g_voxf + ((size_t)col*ZW + (z-13))*8;
                    red_v4(base,     w, ft1*w, ft2*w, ft3*w);
                    red_v2(base + 4, ft4*w, ft5*w);
                } else {
                    red_f(g_voxw + (size_t)col*80 + z, w);
                }
            }
        }
    }

    // ---- ks block max (channels 4..7 == ft1..ft4) ----
    float m1=ft1, m2=ft2, m3=ft3, m4=ft4;
    #pragma unroll
    for (int off=16; off; off>>=1) {
        m1 = fmaxf(m1, __shfl_xor_sync(0xffffffffu, m1, off));
        m2 = fmaxf(m2, __shfl_xor_sync(0xffffffffu, m2, off));
        m3 = fmaxf(m3, __shfl_xor_sync(0xffffffffu, m3, off));
        m4 = fmaxf(m4, __shfl_xor_sync(0xffffffffu, m4, off));
    }
    int lane = tid & 31, wid = tid >> 5;
    if (lane == 0) { smax[wid][0]=m1; smax[wid][1]=m2; smax[wid][2]=m3; smax[wid][3]=m4; }
    __syncthreads();
    if (tid < 4) {
        float v = smax[0][tid];
        #pragma unroll
        for (int w=1; w<8; w++) v = fmaxf(v, smax[w][tid]);
        g_bmax[tid*SPLAT_BLOCKS + sblock] = v;
    }
}

// ---------------------------------------------------------------- round + z-sums (+rezero, +ks final)
__global__ __launch_bounds__(256) void reduce_kernel(float* __restrict__ out_fp) {
    int gid = blockIdx.x*256 + threadIdx.x;
    if (gid < 10000) {
        int tv = gid;                       // voxel column index = b*100 + a
        int b = tv / 100, a = tv - b*100;
        int t = a*100 + b;                  // output/agent-view index
        const float4 z4 = make_float4(0.f,0.f,0.f,0.f);

        float allw = 0.f;
        float4* wp = reinterpret_cast<float4*>(g_voxw + (size_t)tv*80);
        #pragma unroll 5
        for (int zi = 0; zi < 20; zi++) {
            float4 v = wp[zi];
            wp[zi] = z4;
            allw += rintf(v.x) + rintf(v.y) + rintf(v.z) + rintf(v.w);
        }

        float ahw = 0.f, ahf[5] = {0.f,0.f,0.f,0.f,0.f};
        float4* fp = reinterpret_cast<float4*>(g_voxf + (size_t)tv*ZW*8);
        #pragma unroll
        for (int wz = 0; wz < ZW; wz++) {
            float4 v0 = fp[wz*2], v1 = fp[wz*2+1];
            fp[wz*2] = z4; fp[wz*2+1] = z4;
            ahw += rintf(v0.x);
            ahf[0] += rintf(v0.y); ahf[1] += rintf(v0.z); ahf[2] += rintf(v0.w);
            ahf[3] += rintf(v1.x); ahf[4] += rintf(v1.y);
        }
        allw += ahw;

        float r0 = fminf(fmaxf(ahw,  0.f), 1.f);
        g_av[          t] = r0;
        g_av[  10000 + t] = fminf(fmaxf(allw, 0.f), 1.f);
        #pragma unroll
        for (int c=0;c<5;c++)
            g_av[(2+c)*10000 + t] = fminf(fmaxf(ahf[c]/5.0f, 0.f), 1.f);
        out_fp[t] = r0;
    } else {
        int kid = gid - 10000;
        if (kid < 128) {
            int ch = kid >> 5, lane = kid & 31;
            float m = 0.0f;
            for (int i = lane; i < SPLAT_BLOCKS; i += 32)
                m = fmaxf(m, g_bmax[ch*SPLAT_BLOCKS + i]);
            #pragma unroll
            for (int off=16; off; off>>=1) m = fmaxf(m, __shfl_xor_sync(0xffffffffu, m, off));
            if (lane == 0) g_ks[ch] = m;
        }
    }
}

// ---------------------------------------------------------------- rotation resample (support window only)
__global__ __launch_bounds__(256) void rotate_kernel() {
    int idx = blockIdx.x*256 + threadIdx.x;
    if (idx >= ROT_W*ROT_W) return;
    int i = ROT_LO + idx / ROT_W, j = ROT_LO + idx % ROT_W;
    int xmin = (int)g_params[5], xmax = (int)g_params[6];
    int ymin = (int)g_params[7], ymax = (int)g_params[8];
    if (j < xmin || j > xmax || i < ymin || i > ymax) return;
    float ct = g_params[1], sn = g_params[2];
    const float step = 2.0f/959.0f;
    float gx = -1.0f + (float)j*step;
    float gy = -1.0f + (float)i*step;
    float x = (ct*gx - sn*gy + 1.0f)*0.5f*959.0f;
    float y = (sn*gx + ct*gy + 1.0f)*0.5f*959.0f;
    float x0 = floorf(x), y0 = floorf(y);
    float acc[7] = {0.f,0.f,0.f,0.f,0.f,0.f,0.f};
    #pragma unroll
    for (int dy=0; dy<2; dy++){
        float yy = y0 + (float)dy;
        int yi = (int)yy;
        #pragma unroll
        for (int dx=0; dx<2; dx++){
            float xx = x0 + (float)dx;
            int xi = (int)xx;
            if (yi >= 480 && yi < 580 && xi >= 430 && xi < 530) {
                float wv = (1.0f - fabsf(x - xx)) * (1.0f - fabsf(y - yy));
                int o = (yi - 480)*100 + (xi - 430);
                #pragma unroll
                for (int c=0;c<7;c++) acc[c] += g_av[c*10000 + o] * wv;
            }
        }
    }
    #pragma unroll
    for (int c=0;c<7;c++) g_rot[c*MPIX + i*MM + j] = acc[c];
}

// ---------------------------------------------------------------- fix: dirty quads inside the window
__global__ __launch_bounds__(256) void fix_kernel(const float* __restrict__ maps_last,
                                                  float* __restrict__ out_map) {
    int idx = blockIdx.x*256 + threadIdx.x;
    if (idx >= FIX_THREADS) return;
    int ch7 = idx / (48*FIXW);               // 0..6: t-channel index
    int rr  = idx - ch7*(48*FIXW);
    int qy  = rr / 48, qx = rr - qy*48;
    int ox = g_win[0], oy = g_win[1];
    int i  = oy + qy;
    int j0 = ox + qx*4;

    float xminf = g_params[5], xmaxf = g_params[6];
    float yminf = g_params[7], ymaxf = g_params[8];
    float dxs = g_params[9],  dys = g_params[10];
    if (!quad_dirty(i, j0, xminf, xmaxf, yminf, ymaxf, dxs, dys)) return;

    const float step = 2.0f/959.0f;
    float sx = g_params[3], sy = g_params[4];
    float gy = -1.0f + (float)i*step;
    float y = ((gy + sy) + 1.0f)*0.5f*959.0f;
    float y0 = floorf(y);

    float t[4] = {0.f,0.f,0.f,0.f};
    #pragma unroll
    for (int l=0;l<4;l++){
        float gx = -1.0f + (float)(j0+l)*step;
        float x = ((gx + sx) + 1.0f)*0.5f*959.0f;
        float x0 = floorf(x);
        #pragma unroll
        for (int dy=0; dy<2; dy++){
            float yy = y0 + (float)dy;
            int yi = (int)yy;
            #pragma unroll
            for (int dx=0; dx<2; dx++){
                float xx = x0 + (float)dx;
                int xi = (int)xx;
                if (xx >= 0.0f && xx <= 959.0f && yy >= 0.0f && yy <= 959.0f) {
                    float wv = (1.0f - fabsf(x - xx)) * (1.0f - fabsf(y - yy));
                    t[l] += g_rot[ch7*MPIX + yi*MM + xi] * wv;
                }
            }
        }
    }
    if (ch7 >= 2 && ch7 <= 5) {               // sem channels: replace positives with ks
        float ks = g_ks[ch7-2];
        #pragma unroll
        for (int l=0;l<4;l++) t[l] = t[l] > 0.0f ? ks : t[l];
    }
    int och = (ch7 == 0) ? 0 : (ch7 == 1) ? 1 : (ch7 <= 5) ? (ch7 + 2) : 8;
    int v = och*VQ + (i*MM + j0)/4;
    float4 m = reinterpret_cast<const float4*>(maps_last)[v];
    reinterpret_cast<float4*>(out_map)[v] =
        make_float4(fmaxf(m.x,t[0]), fmaxf(m.y,t[1]), fmaxf(m.z,t[2]), fmaxf(m.w,t[3]));
}

// ---------------------------------------------------------------- launch
extern "C" void kernel_launch(void* const* d_in, const int* in_sizes, int n_in,
                              void* d_out, int out_size) {
    const float* obs        = (const float*)d_in[0];   // (1,9,480,640)
    const float* pose_obs   = (const float*)d_in[1];   // (3,)
    const float* maps_last  = (const float*)d_in[2];   // (9,960,960)
    const float* poses_last = (const float*)d_in[3];   // (3,)
    float* out = (float*)d_out;

    pose_kernel<<<1, 1>>>(pose_obs, poses_last, out);
    fused_kernel<<<FUSED_BLOCKS, 256>>>(obs, maps_last, out + MAP_OFF);
    reduce_kernel<<<40, 256>>>(out + FP_OFF);
    rotate_kernel<<<(ROT_W*ROT_W + 255)/256, 256>>>();
    fix_kernel<<<(FIX_THREADS + 255)/256, 256>>>(maps_last, out + MAP_OFF);
    (void)in_sizes; (void)n_in; (void)out_size;
}

// round 15
// speedup vs baseline: 1.3348x; 1.3348x over previous
#include <cuda_runtime.h>
#include <math.h>

#define HH 480
#define WW 640
#define NPIX (HH*WW)          // 307200
#define MM 960
#define MPIX (MM*MM)          // 921600
#define FP_OFF 0
#define MAP_OFF 10000
#define POSE_OFF (10000 + 9*MPIX)   // 8304400
#define SPLAT_BLOCKS 1200
#define FUSED_BLOCKS 9300     // 31 * 300 (4 splat + 27 copy per group)
#define ZW 12                 // window z slots: 13..24
#define VQ (MPIX/4)           // 230400 quads per channel
#define FIXW 192              // fix window (pixels)

// scratch (device globals: allocation-free, zero-initialized at load)
__device__ __align__(16) float g_voxw[100*100*80];      // scalar weight grid, full z (3.2MB)
__device__ __align__(32) float g_voxf[100*100*ZW*8];    // window: [col][wz][8] = w,f1..f5,pad,pad
__device__ __align__(32) float g_av8[10000*8];          // agent view interleaved: r0,fexp,f1..f5,0
__device__ float g_bmax[4*SPLAT_BLOCKS];       // per-block ks maxes
__device__ float g_ks[4];                      // final ks
__device__ float g_params[12];                 // 0:fcam 1:ct 2:sn 3:sx 4:sy 5..8:bbox 9:dxs 10:dys
__device__ int   g_win[2];                     // fix window origin (ox, oy)

__device__ __forceinline__ void red_v4(float* p, float a, float b, float c, float d) {
    asm volatile("red.global.add.v4.f32 [%0], {%1,%2,%3,%4};"
                 :: "l"(p), "f"(a), "f"(b), "f"(c), "f"(d) : "memory");
}
__device__ __forceinline__ void red_v2(float* p, float a, float b) {
    asm volatile("red.global.add.v2.f32 [%0], {%1,%2};"
                 :: "l"(p), "f"(a), "f"(b) : "memory");
}
__device__ __forceinline__ void red_f(float* p, float a) {
    asm volatile("red.global.add.f32 [%0], %1;" :: "l"(p), "f"(a) : "memory");
}

// dirty-quad predicate: evaluated on identical g_params values by both the copy
// path and the fix kernel (identical inputs -> identical boolean).
__device__ __forceinline__ bool quad_dirty(int i, int j0,
                                           float xminf, float xmaxf,
                                           float yminf, float ymaxf,
                                           float dxs, float dys) {
    float ylo = floorf((float)i + dys);
    float xlo = floorf((float)j0 + dxs);
    float xhi = floorf((float)(j0+3) + dxs);
    return (ylo >= yminf - 2.0f) && (ylo <= ymaxf + 2.0f) &&
           (xhi >= xminf - 2.0f) && (xlo <= xmaxf + 2.0f);
}

// ---------------------------------------------------------------- pose/params (single thread)
__global__ void pose_kernel(const float* __restrict__ pose_obs,
                            const float* __restrict__ poses_last,
                            float* __restrict__ out) {
    const float DEGf = 57.29577951308232f;
    float th = poses_last[2] / DEGf;
    float s = sinf(th), c = cosf(th);
    float ny = poses_last[1] + pose_obs[0]*s + pose_obs[1]*c;
    float nx = poses_last[0] + pose_obs[0]*c - pose_obs[1]*s;
    float nt = poses_last[2] + pose_obs[2]*DEGf;
    nt = fmodf(nt - 180.0f, 360.0f) + 180.0f;
    nt = fmodf(nt + 180.0f, 360.0f) - 180.0f;
    out[POSE_OFF+0] = nx; out[POSE_OFF+1] = ny; out[POSE_OFF+2] = nt;
    out[POSE_OFF+3] = nx; out[POSE_OFF+4] = ny; out[POSE_OFF+5] = nt;

    float sx = -(nx*100.0f/5.0f - 480.0f)/480.0f;
    float sy = -(ny*100.0f/5.0f - 480.0f)/480.0f;
    float sth = (90.0f - nt) * 3.14159265358979323846f / 180.0f;
    float ct = cosf(sth), sn = sinf(sth);
    g_params[0] = (float)(320.0 / tan(39.5 * 3.141592653589793 / 180.0));
    g_params[1] = ct; g_params[2] = sn;
    g_params[3] = sx; g_params[4] = sy;

    const float half = 479.5f;
    float xmn=1e9f,xmx=-1e9f,ymn=1e9f,ymx=-1e9f;
    float cx[4] = {429.f,530.f,429.f,530.f};
    float cy[4] = {479.f,479.f,580.f,580.f};
    #pragma unroll
    for (int k=0;k<4;k++){
        float u = cx[k]/half - 1.0f, v = cy[k]/half - 1.0f;
        float gu =  ct*u + sn*v;
        float gv = -sn*u + ct*v;
        float jx = (gu+1.0f)*half, iy = (gv+1.0f)*half;
        xmn = fminf(xmn,jx); xmx = fmaxf(xmx,jx);
        ymn = fminf(ymn,iy); ymx = fmaxf(ymx,iy);
    }
    float xminf = fmaxf(floorf(xmn)-3.0f, 0.0f);
    float xmaxf = fminf(ceilf (xmx)+3.0f, 959.0f);
    float yminf = fmaxf(floorf(ymn)-3.0f, 0.0f);
    float ymaxf = fminf(ceilf (ymx)+3.0f, 959.0f);
    g_params[5] = xminf; g_params[6] = xmaxf;
    g_params[7] = yminf; g_params[8] = ymaxf;
    float dxs = sx*479.5f, dys = sy*479.5f;
    g_params[9] = dxs; g_params[10] = dys;

    int ox = (((int)floorf(xminf - dxs)) - 8) & ~3;
    int oy =  ((int)floorf(yminf - dys)) - 8;
    ox = max(0, min(ox, MM - FIXW));
    oy = max(0, min(oy, MM - FIXW));
    g_win[0] = ox; g_win[1] = oy;
}

// ---------------------------------------------------------------- fused: splat + out-of-bbox map copy
__global__ __launch_bounds__(256) void fused_kernel(const float* __restrict__ obs,
                                                    const float* __restrict__ maps_last,
                                                    float* __restrict__ out_map) {
    int b = blockIdx.x;
    int grp = b / 31, r = b % 31;
    int tid = threadIdx.x;

    if (r >= 4) {
        // ================= copy path: one float4 of one channel per thread
        int cblock = grp*27 + (r - 4);
        int idx = cblock*256 + tid;          // [0, 9*VQ)
        int ch = idx / VQ;                   // uniform per block (VQ % 256 == 0)
        int q  = idx - ch*VQ;
        const float4* ml = reinterpret_cast<const float4*>(maps_last);
        float4*       om = reinterpret_cast<float4*>(out_map);
        if (ch != 2 && ch != 3) {
            int i  = q / (MM/4);
            int j0 = (q - i*(MM/4)) * 4;
            float xminf = g_params[5], xmaxf = g_params[6];
            float yminf = g_params[7], ymaxf = g_params[8];
            float dxs = g_params[9],  dys = g_params[10];
            int ox = g_win[0], oy = g_win[1];
            bool inwin = (i >= oy) && (i < oy + FIXW) && (j0 >= ox) && (j0 < ox + FIXW);
            if (inwin && quad_dirty(i, j0, xminf, xmaxf, yminf, ymaxf, dxs, dys))
                return;                       // fix_kernel owns this quad+channel
        }
        float4 m = ml[idx];
        om[idx] = make_float4(fmaxf(m.x,0.f), fmaxf(m.y,0.f), fmaxf(m.z,0.f), fmaxf(m.w,0.f));
        return;
    }

    // ================= splat path
    __shared__ float smax[8][4];
    int sblock = grp*4 + r;
    float fcam = g_params[0];
    int pix = sblock*256 + tid;              // NPIX == SPLAT_BLOCKS*256 exactly
    int i = pix / WW, j = pix - i*WW;
    float depth = obs[3*NPIX + pix];
    float X = ((float)j - 319.5f) * depth / fcam + 250.0f;
    float Z = ((float)(479 - i) - 239.5f) * depth / fcam + 88.0f;
    float xs = (X/5.0f - 50.0f)/100.0f*2.0f;
    float ys = (depth/5.0f - 50.0f)/100.0f*2.0f;
    float zs = (Z/5.0f - 32.0f)/80.0f*2.0f;
    float pos0 = xs*100.0f/2.0f + 50.0f;
    float pos1 = ys*100.0f/2.0f + 50.0f;
    float pos2 = zs*80.0f/2.0f + 40.0f;
    float fl0 = floorf(pos0), fl1 = floorf(pos1), fl2 = floorf(pos2);
    float ft1 = obs[4*NPIX+pix], ft2 = obs[5*NPIX+pix], ft3 = obs[6*NPIX+pix];
    float ft4 = obs[7*NPIX+pix], ft5 = obs[8*NPIX+pix];

    #pragma unroll
    for (int c0=0;c0<2;c0++){
        float p0 = fl0 + (float)c0;
        if (!(p0 > 0.0f && p0 < 100.0f)) continue;
        float w0 = 1.0f - fabsf(pos0 - p0);
        #pragma unroll
        for (int c1=0;c1<2;c1++){
            float p1 = fl1 + (float)c1;
            if (!(p1 > 0.0f && p1 < 100.0f)) continue;
            float w01 = w0 * (1.0f - fabsf(pos1 - p1));
            int col = ((int)p0)*100 + (int)p1;
            #pragma unroll
            for (int c2=0;c2<2;c2++){
                float p2 = fl2 + (float)c2;
                if (!(p2 > 0.0f && p2 < 80.0f)) continue;
                float w = w01 * (1.0f - fabsf(pos2 - p2));
                int z = (int)p2;
                if (z >= 13 && z < 25) {
                    float* base = g_voxf + ((size_t)col*ZW + (z-13))*8;
                    red_v4(base,     w, ft1*w, ft2*w, ft3*w);
                    red_v2(base + 4, ft4*w, ft5*w);
                } else {
                    red_f(g_voxw + (size_t)col*80 + z, w);
                }
            }
        }
    }

    // ---- ks block max (channels 4..7 == ft1..ft4) ----
    float m1=ft1, m2=ft2, m3=ft3, m4=ft4;
    #pragma unroll
    for (int off=16; off; off>>=1) {
        m1 = fmaxf(m1, __shfl_xor_sync(0xffffffffu, m1, off));
        m2 = fmaxf(m2, __shfl_xor_sync(0xffffffffu, m2, off));
        m3 = fmaxf(m3, __shfl_xor_sync(0xffffffffu, m3, off));
        m4 = fmaxf(m4, __shfl_xor_sync(0xffffffffu, m4, off));
    }
    int lane = tid & 31, wid = tid >> 5;
    if (lane == 0) { smax[wid][0]=m1; smax[wid][1]=m2; smax[wid][2]=m3; smax[wid][3]=m4; }
    __syncthreads();
    if (tid < 4) {
        float v = smax[0][tid];
        #pragma unroll
        for (int w=1; w<8; w++) v = fmaxf(v, smax[w][tid]);
        g_bmax[tid*SPLAT_BLOCKS + sblock] = v;
    }
}

// ---------------------------------------------------------------- round + z-sums (4 threads/col, +rezero, +ks final)
__global__ __launch_bounds__(256) void reduce_kernel(float* __restrict__ out_fp) {
    int gid = blockIdx.x*256 + threadIdx.x;
    if (gid < 40000) {
        int colq = gid >> 2, q = gid & 3;   // 4 threads per column
        int b = colq / 100, a = colq - b*100;
        int t = a*100 + b;                  // output/agent-view index (colq = b*100+a voxel col)
        const float4 z4 = make_float4(0.f,0.f,0.f,0.f);

        // weight grid: 20 float4 per column, 5 per thread
        float allw = 0.f;
        float4* wp = reinterpret_cast<float4*>(g_voxw + (size_t)colq*80) + q*5;
        #pragma unroll
        for (int zi = 0; zi < 5; zi++) {
            float4 v = wp[zi];
            wp[zi] = z4;
            allw += rintf(v.x) + rintf(v.y) + rintf(v.z) + rintf(v.w);
        }

        // window voxels: 12 wz, 3 per thread
        float ahw = 0.f, ahf[5] = {0.f,0.f,0.f,0.f,0.f};
        float4* fp = reinterpret_cast<float4*>(g_voxf + (size_t)colq*ZW*8) + q*6;
        #pragma unroll
        for (int wz = 0; wz < 3; wz++) {
            float4 v0 = fp[wz*2], v1 = fp[wz*2+1];
            fp[wz*2] = z4; fp[wz*2+1] = z4;
            ahw += rintf(v0.x);
            ahf[0] += rintf(v0.y); ahf[1] += rintf(v0.z); ahf[2] += rintf(v0.w);
            ahf[3] += rintf(v1.x); ahf[4] += rintf(v1.y);
        }
        allw += ahw;

        // combine across the 4 threads (lane groups of 4)
        #pragma unroll
        for (int d = 2; d; d >>= 1) {
            allw += __shfl_down_sync(0xffffffffu, allw, d);
            ahw  += __shfl_down_sync(0xffffffffu, ahw,  d);
            #pragma unroll
            for (int c=0;c<5;c++) ahf[c] += __shfl_down_sync(0xffffffffu, ahf[c], d);
        }
        if (q == 0) {
            float r0 = fminf(fmaxf(ahw,  0.f), 1.f);
            float fe = fminf(fmaxf(allw, 0.f), 1.f);
            float f1 = fminf(fmaxf(ahf[0]/5.0f, 0.f), 1.f);
            float f2 = fminf(fmaxf(ahf[1]/5.0f, 0.f), 1.f);
            float f3 = fminf(fmaxf(ahf[2]/5.0f, 0.f), 1.f);
            float f4v= fminf(fmaxf(ahf[3]/5.0f, 0.f), 1.f);
            float f5 = fminf(fmaxf(ahf[4]/5.0f, 0.f), 1.f);
            float4* avp = reinterpret_cast<float4*>(g_av8 + (size_t)t*8);
            avp[0] = make_float4(r0, fe, f1, f2);
            avp[1] = make_float4(f3, f4v, f5, 0.f);
            out_fp[t] = r0;
        }
    } else {
        int kid = gid - 40000;
        if (kid < 128) {
            int ch = kid >> 5, lane = kid & 31;
            float m = 0.0f;
            for (int i = lane; i < SPLAT_BLOCKS; i += 32)
                m = fmaxf(m, g_bmax[ch*SPLAT_BLOCKS + i]);
            #pragma unroll
            for (int off=16; off; off>>=1) m = fmaxf(m, __shfl_xor_sync(0xffffffffu, m, off));
            if (lane == 0) g_ks[ch] = m;
        }
    }
}

// ---------------------------------------------------------------- nested rotate eval at integer pixel (i2,j2)
__device__ __forceinline__ void rotate_eval(int i2, int j2, float ct, float sn, float* rv) {
    const float step = 2.0f/959.0f;
    float gx = -1.0f + (float)j2*step;
    float gy = -1.0f + (float)i2*step;
    float x = (ct*gx - sn*gy + 1.0f)*0.5f*959.0f;
    float y = (sn*gx + ct*gy + 1.0f)*0.5f*959.0f;
    float x0 = floorf(x), y0 = floorf(y);
    #pragma unroll
    for (int c=0;c<7;c++) rv[c] = 0.f;
    #pragma unroll
    for (int dy=0; dy<2; dy++){
        float yy = y0 + (float)dy;
        int yi = (int)yy;
        #pragma unroll
        for (int dx=0; dx<2; dx++){
            float xx = x0 + (float)dx;
            int xi = (int)xx;
            if (yi >= 480 && yi < 580 && xi >= 430 && xi < 530) {
                float wv = (1.0f - fabsf(x - xx)) * (1.0f - fabsf(y - yy));
                const float4* avp = reinterpret_cast<const float4*>(g_av8 + (size_t)((yi-480)*100 + (xi-430))*8);
                float4 a0 = avp[0], a1 = avp[1];
                rv[0] += a0.x*wv; rv[1] += a0.y*wv; rv[2] += a0.z*wv;
                rv[3] += a0.w*wv; rv[4] += a1.x*wv; rv[5] += a1.y*wv;
                rv[6] += a1.z*wv;
            }
        }
    }
}

// ---------------------------------------------------------------- fix: dirty pixels, nested rotate+translate
__global__ __launch_bounds__(256) void fix_kernel(const float* __restrict__ maps_last,
                                                  float* __restrict__ out_map) {
    int idx = blockIdx.x*256 + threadIdx.x;
    if (idx >= FIXW*FIXW) return;
    int ox = g_win[0], oy = g_win[1];
    int qy = idx / FIXW, qc = idx - qy*FIXW;
    int i = oy + qy;
    int j = ox + qc;
    int j0 = ox + (qc & ~3);                 // quad origin (ox is 4-aligned)

    float xminf = g_params[5], xmaxf = g_params[6];
    float yminf = g_params[7], ymaxf = g_params[8];
    float dxs = g_params[9],  dys = g_params[10];
    if (!quad_dirty(i, j0, xminf, xmaxf, yminf, ymaxf, dxs, dys)) return;

    const float step = 2.0f/959.0f;
    float sx = g_params[3], sy = g_params[4];
    float ct = g_params[1], sn = g_params[2];
    float gy = -1.0f + (float)i*step;
    float gx = -1.0f + (float)j*step;
    float y = ((gy + sy) + 1.0f)*0.5f*959.0f;
    float x = ((gx + sx) + 1.0f)*0.5f*959.0f;
    float y0 = floorf(y), x0 = floorf(x);

    float t[7] = {0.f,0.f,0.f,0.f,0.f,0.f,0.f};
    #pragma unroll
    for (int dy=0; dy<2; dy++){
        float yy = y0 + (float)dy;
        int yi = (int)yy;
        #pragma unroll
        for (int dx=0; dx<2; dx++){
            float xx = x0 + (float)dx;
            int xi = (int)xx;
            if (xx >= 0.0f && xx <= 959.0f && yy >= 0.0f && yy <= 959.0f) {
                float wv = (1.0f - fabsf(x - xx)) * (1.0f - fabsf(y - yy));
                float rv[7];
                rotate_eval(yi, xi, ct, sn, rv);
                #pragma unroll
                for (int c=0;c<7;c++) t[c] += rv[c] * wv;
            }
        }
    }
    // sem replacement on channels 2..5 (-> out ch 4..7)
    #pragma unroll
    for (int k=0;k<4;k++){
        float v = t[2+k];
        t[2+k] = v > 0.0f ? g_ks[k] : v;
    }
    int base = i*MM + j;
    const int ochs[7] = {0,1,4,5,6,7,8};
    #pragma unroll
    for (int c=0;c<7;c++){
        int off = ochs[c]*MPIX + base;
        out_map[off] = fmaxf(maps_last[off], t[c]);
    }
}

// ---------------------------------------------------------------- launch
extern "C" void kernel_launch(void* const* d_in, const int* in_sizes, int n_in,
                              void* d_out, int out_size) {
    const float* obs        = (const float*)d_in[0];   // (1,9,480,640)
    const float* pose_obs   = (const float*)d_in[1];   // (3,)
    const float* maps_last  = (const float*)d_in[2];   // (9,960,960)
    const float* poses_last = (const float*)d_in[3];   // (3,)
    float* out = (float*)d_out;

    pose_kernel<<<1, 1>>>(pose_obs, poses_last, out);
    fused_kernel<<<FUSED_BLOCKS, 256>>>(obs, maps_last, out + MAP_OFF);
    reduce_kernel<<<157, 256>>>(out + FP_OFF);            // 40192 threads: 4/col + ks tail
    fix_kernel<<<(FIXW*FIXW + 255)/256, 256>>>(maps_last, out + MAP_OFF);
    (void)in_sizes; (void)n_in; (void)out_size;
}